// round 2
// baseline (speedup 1.0000x reference)
#include <cuda_runtime.h>
#include <cstdint>

// Problem constants: N_NODES=50000, N_EDGES=800000, IN=128, HID=128, OUT=64.
// Scratch as __device__ globals (no allocation allowed).
#define NMAX 50048
#define IN_DIM 128
#define HID_DIM 128
#define OUT_DIM 64

__device__ float g_deg[NMAX];              // degree -> dinv (in place)
__device__ float g_h1[NMAX * HID_DIM];     // x @ W1
__device__ float g_acc1[NMAX * HID_DIM];   // scatter target layer 1 (init b1)
__device__ float g_h2[NMAX * OUT_DIM];     // relu(acc1) @ W2

// ---------------------------------------------------------------------------
// degree: atomicAdd unit weight at dst (int32 indices!)
__global__ void deg_kernel(const int* __restrict__ dst, float* __restrict__ deg, int E) {
    int i = blockIdx.x * blockDim.x + threadIdx.x;
    if (i < E) atomicAdd(&deg[dst[i]], 1.0f);
}

// deg -> dinv = deg>0 ? rsqrt(deg) : 0   (in place)
__global__ void dinv_kernel(float* __restrict__ deg, int N) {
    int i = blockIdx.x * blockDim.x + threadIdx.x;
    if (i < N) {
        float d = deg[i];
        deg[i] = d > 0.0f ? rsqrtf(d) : 0.0f;
    }
}

// out[n][c] = b[c]  (bias folded into scatter accumulator init)
template <int C>
__global__ void init_bias_kernel(float* __restrict__ out, const float* __restrict__ b, int N) {
    int i = blockIdx.x * blockDim.x + threadIdx.x;
    if (i < N * C) out[i] = b[i & (C - 1)];
}

// ---------------------------------------------------------------------------
// Tiled fp32 GEMM: Y[M,N] = (RELU? relu(X) : X)[M,K] @ W[K,N]
// 256 threads, 64-row tile, W fully resident in smem, micro-tile 8 x (N/32).
template <int K, int N, bool RELU>
__global__ void gemm_kernel(const float* __restrict__ X, const float* __restrict__ W,
                            float* __restrict__ Y, int M) {
    constexpr int ROWS = 64;
    constexpr int CPT = N / 32;  // cols per thread: 4 (N=128) or 2 (N=64)
    extern __shared__ float smem[];
    float* Ws = smem;              // K*N
    float* Xs = smem + K * N;      // ROWS*K

    int t = threadIdx.x;
    for (int i = t; i < K * N / 4; i += 256)
        ((float4*)Ws)[i] = ((const float4*)W)[i];

    int row0 = blockIdx.x * ROWS;
    for (int i = t; i < ROWS * K / 4; i += 256) {
        int r = i / (K / 4);
        int gr = row0 + r;
        float4 v = make_float4(0.f, 0.f, 0.f, 0.f);
        if (gr < M) v = ((const float4*)X)[(size_t)gr * (K / 4) + (i % (K / 4))];
        if (RELU) {
            v.x = fmaxf(v.x, 0.f); v.y = fmaxf(v.y, 0.f);
            v.z = fmaxf(v.z, 0.f); v.w = fmaxf(v.w, 0.f);
        }
        ((float4*)Xs)[i] = v;
    }
    __syncthreads();

    int tx = t & 31;   // col group
    int ty = t >> 5;   // row group (0..7), 8 rows each
    float acc[8][CPT];
#pragma unroll
    for (int r = 0; r < 8; r++)
#pragma unroll
        for (int c = 0; c < CPT; c++) acc[r][c] = 0.f;

#pragma unroll 4
    for (int k = 0; k < K; k++) {
        float b[CPT];
#pragma unroll
        for (int c = 0; c < CPT; c++) b[c] = Ws[k * N + tx * CPT + c];
#pragma unroll
        for (int r = 0; r < 8; r++) {
            float a = Xs[(ty * 8 + r) * K + k];
#pragma unroll
            for (int c = 0; c < CPT; c++) acc[r][c] += a * b[c];
        }
    }

#pragma unroll
    for (int r = 0; r < 8; r++) {
        int gr = row0 + ty * 8 + r;
        if (gr < M) {
#pragma unroll
            for (int c = 0; c < CPT; c++)
                Y[(size_t)gr * N + tx * CPT + c] = acc[r][c];
        }
    }
}

// ---------------------------------------------------------------------------
// Scatter, C=128: one warp per edge; lane handles one float4 (32*16B=512B/edge).
// red.global.add.v4.f32 (no return) -> 4x fewer L2 atomic ops than scalar.
__global__ void scatter128_kernel(const int* __restrict__ src,
                                  const int* __restrict__ dst,
                                  const float* __restrict__ dinv,
                                  const float* __restrict__ h,
                                  float* __restrict__ out, int E) {
    int gid = blockIdx.x * blockDim.x + threadIdx.x;
    int e = gid >> 5;
    int lane = gid & 31;
    if (e >= E) return;
    int s = src[e];
    int d = dst[e];
    float norm = dinv[s] * dinv[d];
    float4 v = ((const float4*)h)[(size_t)s * 32 + lane];
    float4* o = ((float4*)out) + (size_t)d * 32 + lane;
    asm volatile("red.global.add.v4.f32 [%0], {%1,%2,%3,%4};"
                 :: "l"(o), "f"(v.x * norm), "f"(v.y * norm),
                    "f"(v.z * norm), "f"(v.w * norm)
                 : "memory");
}

// Scatter, C=64: half-warp per edge (16 lanes x float4 = 256B/edge).
__global__ void scatter64_kernel(const int* __restrict__ src,
                                 const int* __restrict__ dst,
                                 const float* __restrict__ dinv,
                                 const float* __restrict__ h,
                                 float* __restrict__ out, int E) {
    int gid = blockIdx.x * blockDim.x + threadIdx.x;
    int e = gid >> 4;
    int lane = gid & 15;
    if (e >= E) return;
    int s = src[e];
    int d = dst[e];
    float norm = dinv[s] * dinv[d];
    float4 v = ((const float4*)h)[(size_t)s * 16 + lane];
    float4* o = ((float4*)out) + (size_t)d * 16 + lane;
    asm volatile("red.global.add.v4.f32 [%0], {%1,%2,%3,%4};"
                 :: "l"(o), "f"(v.x * norm), "f"(v.y * norm),
                    "f"(v.z * norm), "f"(v.w * norm)
                 : "memory");
}

// ---------------------------------------------------------------------------
extern "C" void kernel_launch(void* const* d_in, const int* in_sizes, int n_in,
                              void* d_out, int out_size) {
    const float* x  = (const float*)d_in[0];
    const int*   ei = (const int*)d_in[1];   // JAX x64 disabled -> int32 indices
    const float* W1 = (const float*)d_in[2];
    const float* b1 = (const float*)d_in[3];
    const float* W2 = (const float*)d_in[4];
    const float* b2 = (const float*)d_in[5];
    float* out = (float*)d_out;

    const int N = in_sizes[0] / IN_DIM;
    const int E = in_sizes[1] / 2;
    const int* src = ei;
    const int* dst = ei + E;

    float *p_deg, *p_h1, *p_acc1, *p_h2;
    cudaGetSymbolAddress((void**)&p_deg,  g_deg);
    cudaGetSymbolAddress((void**)&p_h1,   g_h1);
    cudaGetSymbolAddress((void**)&p_acc1, g_acc1);
    cudaGetSymbolAddress((void**)&p_h2,   g_h2);

    const int smem1 = (IN_DIM * HID_DIM + 64 * IN_DIM) * 4;   // 96 KB
    const int smem2 = (HID_DIM * OUT_DIM + 64 * HID_DIM) * 4; // 64 KB
    cudaFuncSetAttribute(gemm_kernel<IN_DIM, HID_DIM, false>,
                         cudaFuncAttributeMaxDynamicSharedMemorySize, smem1);
    cudaFuncSetAttribute(gemm_kernel<HID_DIM, OUT_DIM, true>,
                         cudaFuncAttributeMaxDynamicSharedMemorySize, smem2);

    // 1) degree -> dinv
    cudaMemsetAsync(p_deg, 0, (size_t)N * sizeof(float));
    deg_kernel<<<(E + 255) / 256, 256>>>(dst, p_deg, E);
    dinv_kernel<<<(N + 255) / 256, 256>>>(p_deg, N);

    // 2) layer 1: h1 = x @ W1 ; acc1 = b1 ; scatter norm*h1[src] into acc1
    gemm_kernel<IN_DIM, HID_DIM, false><<<(N + 63) / 64, 256, smem1>>>(x, W1, p_h1, N);
    init_bias_kernel<HID_DIM><<<((size_t)N * HID_DIM + 255) / 256, 256>>>(p_acc1, b1, N);
    {
        long long threads = (long long)E * 32;
        scatter128_kernel<<<(unsigned)((threads + 255) / 256), 256>>>(src, dst, p_deg, p_h1, p_acc1, E);
    }

    // 3) layer 2: h2 = relu(acc1) @ W2 ; out = b2 ; scatter -> out
    gemm_kernel<HID_DIM, OUT_DIM, true><<<(N + 63) / 64, 256, smem2>>>(p_acc1, W2, p_h2, N);
    init_bias_kernel<OUT_DIM><<<((size_t)N * OUT_DIM + 255) / 256, 256>>>(out, b2, N);
    {
        long long threads = (long long)E * 16;
        scatter64_kernel<<<(unsigned)((threads + 255) / 256), 256>>>(src, dst, p_deg, p_h2, out, E);
    }
}

// round 3
// speedup vs baseline: 1.0677x; 1.0677x over previous
#include <cuda_runtime.h>
#include <cstdint>

// N_NODES=50000, N_EDGES=800000, IN=128, HID=128, OUT=64. int32 edge indices.
#define NMAX 50048
#define IN_DIM 128
#define HID_DIM 128
#define OUT_DIM 64

__device__ float g_deg[NMAX];              // degree -> dinv (in place)
__device__ float g_h1[NMAX * HID_DIM];     // dinv[row] * (x @ W1)
__device__ float g_acc1[NMAX * HID_DIM];   // scatter target layer 1 (zero-init)
__device__ float g_h2[NMAX * OUT_DIM];     // dinv[row] * (relu(acc1+b1) @ W2)

// ---------------------------------------------------------------------------
__global__ void deg_kernel(const int* __restrict__ dst, float* __restrict__ deg, int E) {
    int i = blockIdx.x * blockDim.x + threadIdx.x;
    if (i < E) atomicAdd(&deg[dst[i]], 1.0f);   // unused result -> RED
}

__global__ void dinv_kernel(float* __restrict__ deg, int N) {
    int i = blockIdx.x * blockDim.x + threadIdx.x;
    if (i < N) {
        float d = deg[i];
        deg[i] = d > 0.0f ? rsqrtf(d) : 0.0f;
    }
}

// out[n][c] = b[c], float4-vectorized (C multiple of 4)
template <int C>
__global__ void init_bias_kernel(float4* __restrict__ out, const float4* __restrict__ b, int N) {
    int i = blockIdx.x * blockDim.x + threadIdx.x;
    constexpr int C4 = C / 4;
    if (i < N * C4) out[i] = b[i % C4];
}

// ---------------------------------------------------------------------------
// Tiled fp32 GEMM: Y[M,N] = act(X + bias)[M,K] @ W[K,N], then Y[row] *= scale[row].
// act = relu if RELU_BIAS. 256 threads, 64-row tile, W resident in smem.
// Micro-tile: 8 rows x CPT cols. b-loads vectorized (conflict-free), a broadcast.
template <int K, int N, bool RELU_BIAS, bool SCALE>
__global__ void gemm_kernel(const float* __restrict__ X, const float* __restrict__ W,
                            const float* __restrict__ bias, const float* __restrict__ scale,
                            float* __restrict__ Y, int M) {
    constexpr int ROWS = 64;
    constexpr int CPT = N / 32;  // 4 (N=128) or 2 (N=64)
    extern __shared__ float smem[];
    float* Ws = smem;              // K*N
    float* Xs = smem + K * N;      // ROWS*K

    int t = threadIdx.x;
    for (int i = t; i < K * N / 4; i += 256)
        ((float4*)Ws)[i] = ((const float4*)W)[i];

    int row0 = blockIdx.x * ROWS;
    constexpr int K4 = K / 4;
    for (int i = t; i < ROWS * K4; i += 256) {
        int r = i / K4;
        int gr = row0 + r;
        float4 v = make_float4(0.f, 0.f, 0.f, 0.f);
        if (gr < M) v = ((const float4*)X)[(size_t)gr * K4 + (i % K4)];
        if (RELU_BIAS) {
            float4 bb = ((const float4*)bias)[i % K4];
            v.x = fmaxf(v.x + bb.x, 0.f); v.y = fmaxf(v.y + bb.y, 0.f);
            v.z = fmaxf(v.z + bb.z, 0.f); v.w = fmaxf(v.w + bb.w, 0.f);
        }
        ((float4*)Xs)[i] = v;
    }
    __syncthreads();

    int tx = t & 31;   // col group (lane)
    int ty = t >> 5;   // row group (warp)

    if constexpr (CPT == 4) {
        float4 acc[8];
#pragma unroll
        for (int r = 0; r < 8; r++) acc[r] = make_float4(0.f, 0.f, 0.f, 0.f);
#pragma unroll 4
        for (int k = 0; k < K; k += 4) {
            float4 bv[4];
#pragma unroll
            for (int j = 0; j < 4; j++)
                bv[j] = *(const float4*)&Ws[(k + j) * N + tx * 4];
#pragma unroll
            for (int r = 0; r < 8; r++) {
                float4 av = *(const float4*)&Xs[(ty * 8 + r) * K + k];
                acc[r].x += av.x * bv[0].x + av.y * bv[1].x + av.z * bv[2].x + av.w * bv[3].x;
                acc[r].y += av.x * bv[0].y + av.y * bv[1].y + av.z * bv[2].y + av.w * bv[3].y;
                acc[r].z += av.x * bv[0].z + av.y * bv[1].z + av.z * bv[2].z + av.w * bv[3].z;
                acc[r].w += av.x * bv[0].w + av.y * bv[1].w + av.z * bv[2].w + av.w * bv[3].w;
            }
        }
#pragma unroll
        for (int r = 0; r < 8; r++) {
            int gr = row0 + ty * 8 + r;
            if (gr < M) {
                float s = SCALE ? scale[gr] : 1.0f;
                float4 o = acc[r];
                o.x *= s; o.y *= s; o.z *= s; o.w *= s;
                *(float4*)&Y[(size_t)gr * N + tx * 4] = o;
            }
        }
    } else {
        float2 acc[8];
#pragma unroll
        for (int r = 0; r < 8; r++) acc[r] = make_float2(0.f, 0.f);
#pragma unroll 4
        for (int k = 0; k < K; k += 4) {
            float2 bv[4];
#pragma unroll
            for (int j = 0; j < 4; j++)
                bv[j] = *(const float2*)&Ws[(k + j) * N + tx * 2];
#pragma unroll
            for (int r = 0; r < 8; r++) {
                float4 av = *(const float4*)&Xs[(ty * 8 + r) * K + k];
                acc[r].x += av.x * bv[0].x + av.y * bv[1].x + av.z * bv[2].x + av.w * bv[3].x;
                acc[r].y += av.x * bv[0].y + av.y * bv[1].y + av.z * bv[2].y + av.w * bv[3].y;
            }
        }
#pragma unroll
        for (int r = 0; r < 8; r++) {
            int gr = row0 + ty * 8 + r;
            if (gr < M) {
                float s = SCALE ? scale[gr] : 1.0f;
                float2 o = acc[r];
                o.x *= s; o.y *= s;
                *(float2*)&Y[(size_t)gr * N + tx * 2] = o;
            }
        }
    }
}

// ---------------------------------------------------------------------------
// Scatter, C=128: one warp per edge; lane handles one float4 (512B/edge).
// h is prescaled by dinv[src]; only dinv[dst] needed here.
__global__ void scatter128_kernel(const int* __restrict__ src,
                                  const int* __restrict__ dst,
                                  const float* __restrict__ dinv,
                                  const float* __restrict__ h,
                                  float* __restrict__ out, int E) {
    int gid = blockIdx.x * blockDim.x + threadIdx.x;
    int e = gid >> 5;
    int lane = gid & 31;
    if (e >= E) return;
    int s = src[e];
    int d = dst[e];
    float norm = dinv[d];
    float4 v = ((const float4*)h)[(size_t)s * 32 + lane];
    float4* o = ((float4*)out) + (size_t)d * 32 + lane;
    asm volatile("red.global.add.v4.f32 [%0], {%1,%2,%3,%4};"
                 :: "l"(o), "f"(v.x * norm), "f"(v.y * norm),
                    "f"(v.z * norm), "f"(v.w * norm)
                 : "memory");
}

// Scatter, C=64: half-warp per edge (256B/edge).
__global__ void scatter64_kernel(const int* __restrict__ src,
                                 const int* __restrict__ dst,
                                 const float* __restrict__ dinv,
                                 const float* __restrict__ h,
                                 float* __restrict__ out, int E) {
    int gid = blockIdx.x * blockDim.x + threadIdx.x;
    int e = gid >> 4;
    int lane = gid & 15;
    if (e >= E) return;
    int s = src[e];
    int d = dst[e];
    float norm = dinv[d];
    float4 v = ((const float4*)h)[(size_t)s * 16 + lane];
    float4* o = ((float4*)out) + (size_t)d * 16 + lane;
    asm volatile("red.global.add.v4.f32 [%0], {%1,%2,%3,%4};"
                 :: "l"(o), "f"(v.x * norm), "f"(v.y * norm),
                    "f"(v.z * norm), "f"(v.w * norm)
                 : "memory");
}

// ---------------------------------------------------------------------------
extern "C" void kernel_launch(void* const* d_in, const int* in_sizes, int n_in,
                              void* d_out, int out_size) {
    const float* x  = (const float*)d_in[0];
    const int*   ei = (const int*)d_in[1];
    const float* W1 = (const float*)d_in[2];
    const float* b1 = (const float*)d_in[3];
    const float* W2 = (const float*)d_in[4];
    const float* b2 = (const float*)d_in[5];
    float* out = (float*)d_out;

    const int N = in_sizes[0] / IN_DIM;
    const int E = in_sizes[1] / 2;
    const int* src = ei;
    const int* dst = ei + E;

    float *p_deg, *p_h1, *p_acc1, *p_h2;
    cudaGetSymbolAddress((void**)&p_deg,  g_deg);
    cudaGetSymbolAddress((void**)&p_h1,   g_h1);
    cudaGetSymbolAddress((void**)&p_acc1, g_acc1);
    cudaGetSymbolAddress((void**)&p_h2,   g_h2);

    const int smem1 = (IN_DIM * HID_DIM + 64 * IN_DIM) * 4;   // 96 KB
    const int smem2 = (HID_DIM * OUT_DIM + 64 * HID_DIM) * 4; // 64 KB
    cudaFuncSetAttribute((const void*)gemm_kernel<IN_DIM, HID_DIM, false, true>,
                         cudaFuncAttributeMaxDynamicSharedMemorySize, smem1);
    cudaFuncSetAttribute((const void*)gemm_kernel<HID_DIM, OUT_DIM, true, true>,
                         cudaFuncAttributeMaxDynamicSharedMemorySize, smem2);

    // 1) degree -> dinv
    cudaMemsetAsync(p_deg, 0, (size_t)N * sizeof(float));
    deg_kernel<<<(E + 255) / 256, 256>>>(dst, p_deg, E);
    dinv_kernel<<<(N + 255) / 256, 256>>>(p_deg, N);

    // 2) layer 1: h1 = dinv .* (x @ W1); acc1 = 0; scatter dinv[d]*h1[s] += acc1
    gemm_kernel<IN_DIM, HID_DIM, false, true>
        <<<(N + 63) / 64, 256, smem1>>>(x, W1, nullptr, p_deg, p_h1, N);
    cudaMemsetAsync(p_acc1, 0, (size_t)N * HID_DIM * sizeof(float));
    {
        long long threads = (long long)E * 32;
        scatter128_kernel<<<(unsigned)((threads + 255) / 256), 256>>>(src, dst, p_deg, p_h1, p_acc1, E);
    }

    // 3) layer 2: h2 = dinv .* (relu(acc1 + b1) @ W2); out = b2; scatter -> out
    gemm_kernel<HID_DIM, OUT_DIM, true, true>
        <<<(N + 63) / 64, 256, smem2>>>(p_acc1, W2, b1, p_deg, p_h2, N);
    init_bias_kernel<OUT_DIM>
        <<<((size_t)N * OUT_DIM / 4 + 255) / 256, 256>>>((float4*)out, (const float4*)b2, N);
    {
        long long threads = (long long)E * 16;
        scatter64_kernel<<<(unsigned)((threads + 255) / 256), 256>>>(src, dst, p_deg, p_h2, out, E);
    }
}